// round 13
// baseline (speedup 1.0000x reference)
#include <cuda_runtime.h>
#include <cstdint>

#define N     8192
#define FIN   512
#define FO    64
#define NW    256
#define INVN  (1.0f/8192.0f)
#define KS    8

// ---- scratch ----
__device__ uint32_t g_Whb[N*32];      // bf16x2-pair-packed Wh: [jblk][f][idx2]
__device__ float    g_Wh1[N];
__device__ float2   g_BD[N];          // (exp(wh2), exp(0.2*wh2))
__device__ float    g_add[N];
__device__ float    g_ep[N], g_en[N];
__device__ float    g_km[N], g_kn[N];
__device__ unsigned g_mask[N*NW];
__device__ unsigned g_maskn[N*NW];
__device__ float    g_hp[N*FO];

__device__ __forceinline__ uint32_t bf16x2(float lo, float hi) {
    uint32_t r; asm("cvt.rn.bf16x2.f32 %0, %1, %2;" : "=r"(r) : "f"(hi), "f"(lo)); return r;
}
__device__ __forceinline__ uint32_t smem_u32(const void* p) {
    uint32_t a;
    asm("{ .reg .u64 t; cvta.to.shared.u64 t, %1; cvt.u32.u64 %0, t; }" : "=r"(a) : "l"(p));
    return a;
}
__device__ __forceinline__ void cp16(uint32_t dst, const void* src) {
    asm volatile("cp.async.ca.shared.global [%0], [%1], 16;" :: "r"(dst), "l"(src));
}
__device__ __forceinline__ void cp8(uint32_t dst, const void* src) {
    asm volatile("cp.async.ca.shared.global [%0], [%1], 8;" :: "r"(dst), "l"(src));
}
__device__ __forceinline__ void mma_bf16(float* d,
        uint32_t a0, uint32_t a1, uint32_t a2, uint32_t a3,
        uint32_t b0, uint32_t b1) {
    asm volatile("mma.sync.aligned.m16n8k16.row.col.f32.bf16.bf16.f32 "
        "{%0,%1,%2,%3}, {%4,%5,%6,%7}, {%8,%9}, {%0,%1,%2,%3};"
        : "+f"(d[0]), "+f"(d[1]), "+f"(d[2]), "+f"(d[3])
        : "r"(a0), "r"(a1), "r"(a2), "r"(a3), "r"(b0), "r"(b1));
}
__device__ __forceinline__ int4 ldcs4(const int* p) {
    int4 v;
    asm volatile("ld.global.cs.v4.s32 {%0,%1,%2,%3}, [%4];"
        : "=r"(v.x), "=r"(v.y), "=r"(v.z), "=r"(v.w) : "l"(p));
    return v;
}

// ============================================================
// Kernel 1: Wh = h @ W (smem-tiled) + Wh1/Wh2/BD epilogue
// + bf16x2-pair-packed output g_Whb
// ============================================================
__global__ void __launch_bounds__(128) k_gemm1(const float* __restrict__ h,
                                               const float* __restrict__ W,
                                               const float* __restrict__ a) {
    __shared__ float Ws[64*64];
    __shared__ float hs[32*64];
    __shared__ float a_s[2*FO];

    int t = threadIdx.x;
    int f2 = t & 31, rg = t >> 5;
    int i0 = blockIdx.x * 32;
    if (t < 2*FO) a_s[t] = a[t];

    float acc[8][2];
    #pragma unroll
    for (int r = 0; r < 8; r++) { acc[r][0] = 0.f; acc[r][1] = 0.f; }

    for (int kt = 0; kt < 8; kt++) {
        __syncthreads();
        #pragma unroll
        for (int q = 0; q < 8; q++) {
            int idx = t + 128*q;
            int kk = idx >> 4, c4 = (idx & 15) * 4;
            *reinterpret_cast<float4*>(&Ws[kk*64 + c4]) =
                *reinterpret_cast<const float4*>(&W[(size_t)(kt*64 + kk)*FO + c4]);
        }
        #pragma unroll
        for (int q = 0; q < 4; q++) {
            int idx = t + 128*q;
            int row = idx >> 4, c4 = (idx & 15) * 4;
            *reinterpret_cast<float4*>(&hs[row*64 + c4]) =
                *reinterpret_cast<const float4*>(&h[(size_t)(i0+row)*FIN + kt*64 + c4]);
        }
        __syncthreads();

        #pragma unroll 8
        for (int kk = 0; kk < 64; kk++) {
            float w0 = Ws[kk*64 + f2];
            float w1 = Ws[kk*64 + f2 + 32];
            #pragma unroll
            for (int r = 0; r < 8; r++) {
                float hv = hs[(rg*8 + r)*64 + kk];
                acc[r][0] = fmaf(hv, w0, acc[r][0]);
                acc[r][1] = fmaf(hv, w1, acc[r][1]);
            }
        }
    }

    // bf16x2-pair-packed output for m16n8k16 B fragments
    {
        int b    = i0 >> 6;
        int base = (i0 & 32) + rg*8;
        int kk2  = base >> 4;
        int hh   = (base >> 3) & 1;
        #pragma unroll
        for (int c = 0; c < 4; c++) {
            int idx2 = (kk2*4 + c)*2 + hh;
            g_Whb[(size_t)(b*64 + f2)*32 + idx2]      = bf16x2(acc[2*c][0], acc[2*c+1][0]);
            g_Whb[(size_t)(b*64 + f2 + 32)*32 + idx2] = bf16x2(acc[2*c][1], acc[2*c+1][1]);
        }
    }

    // fused Wh1/Wh2/BD epilogue
    #pragma unroll
    for (int r = 0; r < 8; r++) {
        float p1 = acc[r][0] * a_s[f2] + acc[r][1] * a_s[f2 + 32];
        float p2 = acc[r][0] * a_s[64 + f2] + acc[r][1] * a_s[96 + f2];
        #pragma unroll
        for (int off = 16; off; off >>= 1) {
            p1 += __shfl_down_sync(0xffffffffu, p1, off);
            p2 += __shfl_down_sync(0xffffffffu, p2, off);
        }
        if (f2 == 0) {
            int row = i0 + rg*8 + r;
            g_Wh1[row] = p1;
            g_BD[row]  = make_float2(expf(p2), expf(0.2f * p2));
        }
    }
}

// ============================================================
// Kernel 2: FUSED adj pass: ballot-pack + softmax sums
// unroll 16 for deeper MLP
// ============================================================
__global__ void k_spack(const int* __restrict__ adj,
                        const int* __restrict__ adjn) {
    int tid = blockIdx.x * 256 + threadIdx.x;
    g_hp[2*tid]     = 0.f;
    g_hp[2*tid + 1] = 0.f;

    int lane = threadIdx.x & 31;
    int i    = blockIdx.x * 8 + (threadIdx.x >> 5);
    float wh1 = g_Wh1[i];
    float ep = expf(wh1);
    float en = expf(0.2f * wh1);
    const int* arow = adj  + (size_t)i * N;
    const int* nrow = adjn + (size_t)i * N;
    int sh = (lane & 7) * 4;

    float Sm0 = 0.f, Sm1 = 0.f, Sn0 = 0.f, Sn1 = 0.f;

    #pragma unroll 16
    for (int k = 0; k < N/128; k++) {
        int jb = k*128 + lane*4;
        int4   av  = ldcs4(&arow[jb]);
        int4   nv  = ldcs4(&nrow[jb]);
        float4 bd0 = *reinterpret_cast<const float4*>(&g_BD[jb]);
        float4 bd1 = *reinterpret_cast<const float4*>(&g_BD[jb + 2]);

        float v0 = fmaxf(ep*bd0.x, en*bd0.y);
        float v1 = fmaxf(ep*bd0.z, en*bd0.w);
        float v2 = fmaxf(ep*bd1.x, en*bd1.y);
        float v3 = fmaxf(ep*bd1.z, en*bd1.w);

        bool bm0 = av.x > 0, bm1 = av.y > 0, bm2 = av.z > 0, bm3 = av.w > 0;
        bool bn0 = nv.x > 0, bn1 = nv.y > 0, bn2 = nv.z > 0, bn3 = nv.w > 0;

        if (bm0) Sm0 += v0;   if (bm1) Sm1 += v1;
        if (bm2) Sm0 += v2;   if (bm3) Sm1 += v3;
        if (bn0) Sn0 += v0;   if (bn1) Sn1 += v1;
        if (bn2) Sn0 += v2;   if (bn3) Sn1 += v3;

        unsigned nm = (unsigned)bm0 | ((unsigned)bm1 << 1)
                    | ((unsigned)bm2 << 2) | ((unsigned)bm3 << 3);
        unsigned nn = (unsigned)bn0 | ((unsigned)bn1 << 1)
                    | ((unsigned)bn2 << 2) | ((unsigned)bn3 << 3);
        unsigned vm = nm << sh;
        unsigned vn = nn << sh;
        vm |= __shfl_xor_sync(0xffffffffu, vm, 1);
        vn |= __shfl_xor_sync(0xffffffffu, vn, 1);
        vm |= __shfl_xor_sync(0xffffffffu, vm, 2);
        vn |= __shfl_xor_sync(0xffffffffu, vn, 2);
        vm |= __shfl_xor_sync(0xffffffffu, vm, 4);
        vn |= __shfl_xor_sync(0xffffffffu, vn, 4);
        if ((lane & 7) == 0) {
            g_mask [(size_t)i*NW + k*4 + (lane>>3)] = vm;
            g_maskn[(size_t)i*NW + k*4 + (lane>>3)] = vn;
        }
    }
    float Sm = Sm0 + Sm1, Sn = Sn0 + Sn1;
    #pragma unroll
    for (int off = 16; off; off >>= 1) {
        Sm += __shfl_xor_sync(0xffffffffu, Sm, off);
        Sn += __shfl_xor_sync(0xffffffffu, Sn, off);
    }
    if (lane == 0) {
        g_km[i]  = (Sm > 0.f) ? 1.f / Sm : 0.f;
        g_kn[i]  = (Sn > 0.f) ? 1.f / Sn : 0.f;
        g_add[i] = ((Sm > 0.f) ? 0.f : INVN) + ((Sn > 0.f) ? 0.f : INVN);
        g_ep[i]  = ep;
        g_en[i]  = en;
    }
}

// ============================================================
// Kernel 3: fused attention + bf16 m16n8k16 mma, cp.async pipe
// grid (KS=8, N/64); 128 thr = 4 warps x 16 rows; 6 CTAs/SM
// ============================================================
#define WHS_SZ  9216                   // 64 f x 18 uint2
#define AT_OFF  18432
#define BD_OFF  35840
#define SMEM_SZ 36864
#define TL      ((N/KS)/64)

__device__ __forceinline__ float attn_val(float Bj, float Dj,
        float ep, float en, float km, float kn, float kmn, float add,
        unsigned mb, unsigned nb) {
    float ee = fmaxf(ep * Bj, en * Dj);
    float wsum = (mb & 1u) ? ((nb & 1u) ? kmn : km) : ((nb & 1u) ? kn : 0.f);
    return fmaf(ee, wsum, add);
}

__global__ void __launch_bounds__(128, 6) k_main(float* __restrict__ attn) {
    extern __shared__ char sm[];
    uint32_t sb = smem_u32(sm);

    int t = threadIdx.x, w = t >> 5, lane = t & 31;
    int g = lane >> 2, c = lane & 3;
    int i0 = blockIdx.y * 64;
    int rel0 = w*16 + g, rel1 = rel0 + 8;
    int r0 = i0 + rel0, r1 = i0 + rel1;
    int jcta = blockIdx.x * (N/KS);

    float ep0 = g_ep[r0], en0 = g_en[r0], km0 = g_km[r0], kn0 = g_kn[r0], add0 = g_add[r0];
    float ep1 = g_ep[r1], en1 = g_en[r1], km1 = g_km[r1], kn1 = g_kn[r1], add1 = g_add[r1];
    float kmn0 = km0 + kn0, kmn1 = km1 + kn1;

    float acc[8][4];
    #pragma unroll
    for (int nt = 0; nt < 8; nt++)
        #pragma unroll
        for (int q = 0; q < 4; q++) acc[nt][q] = 0.f;

    float* at_s = reinterpret_cast<float*>(sm + AT_OFF);

    {
        int b = jcta >> 6;
        #pragma unroll
        for (int q = 0; q < 4; q++) {
            int idx = t + 128*q;
            int f = idx >> 3, ch = idx & 7;
            cp16(sb + f*144 + ch*16, &g_Whb[(size_t)(b*64 + f)*32 + ch*4]);
        }
        if (t < 64) cp8(sb + BD_OFF + t*8, &g_BD[jcta + t]);
        asm volatile("cp.async.commit_group;" ::: "memory");
    }
    int wb0 = jcta >> 5;
    uint2 mw0 = *reinterpret_cast<const uint2*>(&g_mask [(size_t)r0*NW + wb0]);
    uint2 nw0 = *reinterpret_cast<const uint2*>(&g_maskn[(size_t)r0*NW + wb0]);
    uint2 mw1 = *reinterpret_cast<const uint2*>(&g_mask [(size_t)r1*NW + wb0]);
    uint2 nw1 = *reinterpret_cast<const uint2*>(&g_maskn[(size_t)r1*NW + wb0]);

    for (int tt = 0; tt < TL; tt++) {
        int buf = tt & 1;
        int j0  = jcta + tt*64;

        uint2 mw0n, nw0n, mw1n, nw1n;
        if (tt + 1 < TL) {
            int nb_ = (tt+1) & 1;
            int bn  = (j0 + 64) >> 6;
            #pragma unroll
            for (int q = 0; q < 4; q++) {
                int idx = t + 128*q;
                int f = idx >> 3, ch = idx & 7;
                cp16(sb + nb_*WHS_SZ + f*144 + ch*16, &g_Whb[(size_t)(bn*64 + f)*32 + ch*4]);
            }
            if (t < 64) cp8(sb + BD_OFF + nb_*512 + t*8, &g_BD[j0 + 64 + t]);
            asm volatile("cp.async.commit_group;" ::: "memory");
            int wbn = (j0 + 64) >> 5;
            mw0n = *reinterpret_cast<const uint2*>(&g_mask [(size_t)r0*NW + wbn]);
            nw0n = *reinterpret_cast<const uint2*>(&g_maskn[(size_t)r0*NW + wbn]);
            mw1n = *reinterpret_cast<const uint2*>(&g_mask [(size_t)r1*NW + wbn]);
            nw1n = *reinterpret_cast<const uint2*>(&g_maskn[(size_t)r1*NW + wbn]);
            asm volatile("cp.async.wait_group 1;" ::: "memory");
        } else {
            mw0n = make_uint2(0,0); nw0n = mw0n; mw1n = mw0n; nw1n = mw0n;
            asm volatile("cp.async.wait_group 0;" ::: "memory");
        }
        __syncthreads();

        const uint2*  whsp = reinterpret_cast<const uint2*>(sm + buf*WHS_SZ);
        const float2* BDs  = reinterpret_cast<const float2*>(sm + BD_OFF + buf*512);

        #pragma unroll
        for (int kk2 = 0; kk2 < 4; kk2++) {
            int jA = kk2*16 + 2*c;
            int jB = jA + 8;
            float4 bdA = *reinterpret_cast<const float4*>(&BDs[jA]);
            float4 bdB = *reinterpret_cast<const float4*>(&BDs[jB]);
            unsigned m0 = (kk2 < 2) ? mw0.x : mw0.y;
            unsigned n0 = (kk2 < 2) ? nw0.x : nw0.y;
            unsigned m1 = (kk2 < 2) ? mw1.x : mw1.y;
            unsigned n1 = (kk2 < 2) ? nw1.x : nw1.y;
            int sA = (kk2 & 1)*16 + 2*c, sB = sA + 8;

            float v00 = attn_val(bdA.x, bdA.y, ep0, en0, km0, kn0, kmn0, add0, m0>>sA,     n0>>sA);
            float v01 = attn_val(bdA.z, bdA.w, ep0, en0, km0, kn0, kmn0, add0, m0>>(sA+1), n0>>(sA+1));
            float v02 = attn_val(bdB.x, bdB.y, ep0, en0, km0, kn0, kmn0, add0, m0>>sB,     n0>>sB);
            float v03 = attn_val(bdB.z, bdB.w, ep0, en0, km0, kn0, kmn0, add0, m0>>(sB+1), n0>>(sB+1));
            float v10 = attn_val(bdA.x, bdA.y, ep1, en1, km1, kn1, kmn1, add1, m1>>sA,     n1>>sA);
            float v11 = attn_val(bdA.z, bdA.w, ep1, en1, km1, kn1, kmn1, add1, m1>>(sA+1), n1>>(sA+1));
            float v12 = attn_val(bdB.x, bdB.y, ep1, en1, km1, kn1, kmn1, add1, m1>>sB,     n1>>sB);
            float v13 = attn_val(bdB.z, bdB.w, ep1, en1, km1, kn1, kmn1, add1, m1>>(sB+1), n1>>(sB+1));

            *reinterpret_cast<float2*>(&at_s[rel0*68 + jA]) = make_float2(v00, v01);
            *reinterpret_cast<float2*>(&at_s[rel0*68 + jB]) = make_float2(v02, v03);
            *reinterpret_cast<float2*>(&at_s[rel1*68 + jA]) = make_float2(v10, v11);
            *reinterpret_cast<float2*>(&at_s[rel1*68 + jB]) = make_float2(v12, v13);

            uint32_t a0 = bf16x2(v00, v01);
            uint32_t a1 = bf16x2(v10, v11);
            uint32_t a2 = bf16x2(v02, v03);
            uint32_t a3 = bf16x2(v12, v13);

            #pragma unroll
            for (int nt = 0; nt < 8; nt++) {
                uint2 b01 = whsp[(nt*8 + g)*18 + kk2*4 + c];
                mma_bf16(acc[nt], a0, a1, a2, a3, b01.x, b01.y);
            }
        }
        mw0 = mw0n; nw0 = nw0n; mw1 = mw1n; nw1 = nw1n;
        __syncthreads();

        #pragma unroll
        for (int q = 0; q < 8; q++) {
            int row = (t >> 4) + 8*q;
            int c4  = (t & 15) * 4;
            float4 v = *reinterpret_cast<const float4*>(&at_s[row*68 + c4]);
            *reinterpret_cast<float4*>(&attn[(size_t)(i0+row)*N + j0 + c4]) = v;
        }
    }

    #pragma unroll
    for (int nt = 0; nt < 8; nt++) {
        atomicAdd(&g_hp[(size_t)r0*FO + nt*8 + 2*c    ], acc[nt][0]);
        atomicAdd(&g_hp[(size_t)r0*FO + nt*8 + 2*c + 1], acc[nt][1]);
        atomicAdd(&g_hp[(size_t)r1*FO + nt*8 + 2*c    ], acc[nt][2]);
        atomicAdd(&g_hp[(size_t)r1*FO + nt*8 + 2*c + 1], acc[nt][3]);
    }
}

// ============================================================
// Kernel 4: out = elu(h_prime), float4
// ============================================================
__global__ void k_elu(float* __restrict__ out) {
    int tid = blockIdx.x * 256 + threadIdx.x;
    float4 x = reinterpret_cast<const float4*>(g_hp)[tid];
    x.x = x.x > 0.f ? x.x : expm1f(x.x);
    x.y = x.y > 0.f ? x.y : expm1f(x.y);
    x.z = x.z > 0.f ? x.z : expm1f(x.z);
    x.w = x.w > 0.f ? x.w : expm1f(x.w);
    reinterpret_cast<float4*>(out)[tid] = x;
}

// ============================================================
extern "C" void kernel_launch(void* const* d_in, const int* in_sizes, int n_in,
                              void* d_out, int out_size) {
    const float* h    = (const float*)d_in[0];
    const float* W    = (const float*)d_in[1];
    const float* a    = (const float*)d_in[2];
    const int*   adj  = (const int*)d_in[3];
    const int*   adjn = (const int*)d_in[4];

    float* out  = (float*)d_out;
    float* attn = out + (size_t)N * FO;

    cudaFuncSetAttribute(k_main, cudaFuncAttributeMaxDynamicSharedMemorySize, SMEM_SZ);

    k_gemm1<<<N/32, 128>>>(h, W, a);
    k_spack<<<N/8, 256>>>(adj, adjn);
    k_main<<<dim3(KS, N/64), 128, SMEM_SZ>>>(attn);
    k_elu<<<(N*FO)/1024, 256>>>(out);
}